// round 7
// baseline (speedup 1.0000x reference)
#include <cuda_runtime.h>
#include <cuda_bf16.h>
#include <cstdint>

#define DIM 128
#define NTH 512
#define PI_F 3.14159265358979323846f

// ---- smem byte offsets ----
#define OFF_W1H 0
#define OFF_W1L 32768
#define OFF_W2H 65536
#define OFF_W2L 98304
#define OFF_AH  131072
#define OFF_AL  163840
#define OFF_B1  196608
#define OFF_B2  197120
#define SMEM_TOTAL 197632

// swizzled byte offset in a [128 rows x 128 k] bf16 tile, 256B/row
__device__ __forceinline__ uint32_t swz(int row, int kElem) {
    return (uint32_t)(row * 256) + (((uint32_t)(kElem * 2)) ^ (uint32_t)((row & 7) << 4));
}

__device__ __forceinline__ uint32_t smem_u32(const void* p) {
    uint32_t a;
    asm("{ .reg .u64 t; cvta.to.shared.u64 t, %1; cvt.u32.u64 %0, t; }" : "=r"(a) : "l"(p));
    return a;
}

__device__ __forceinline__ void ldsm4(uint32_t& r0, uint32_t& r1, uint32_t& r2, uint32_t& r3,
                                      uint32_t addr) {
    asm volatile("ldmatrix.sync.aligned.m8n8.x4.shared.b16 {%0,%1,%2,%3}, [%4];"
                 : "=r"(r0), "=r"(r1), "=r"(r2), "=r"(r3) : "r"(addr));
}

__device__ __forceinline__ void mma16816(float* c, const uint32_t* a, uint32_t b0, uint32_t b1) {
    asm volatile(
        "mma.sync.aligned.m16n8k16.row.col.f32.bf16.bf16.f32 "
        "{%0,%1,%2,%3}, {%4,%5,%6,%7}, {%8,%9}, {%0,%1,%2,%3};"
        : "+f"(c[0]), "+f"(c[1]), "+f"(c[2]), "+f"(c[3])
        : "r"(a[0]), "r"(a[1]), "r"(a[2]), "r"(a[3]), "r"(b0), "r"(b1));
}

__device__ __forceinline__ uint32_t pack2(__nv_bfloat16 a, __nv_bfloat16 b) {
    return ((uint32_t)__bfloat16_as_ushort(b) << 16) | (uint32_t)__bfloat16_as_ushort(a);
}

__device__ __forceinline__ void split2(float x0, float x1, uint32_t& hi, uint32_t& lo) {
    const __nv_bfloat16 h0 = __float2bfloat16(x0), h1 = __float2bfloat16(x1);
    hi = pack2(h0, h1);
    lo = pack2(__float2bfloat16(x0 - __bfloat162float(h0)),
               __float2bfloat16(x1 - __bfloat162float(h1)));
}

__device__ __forceinline__ void split_store(char* sm, int baseHi, int baseLo,
                                            int row, int k, float x0, float x1) {
    const uint32_t off = swz(row, k);
    uint32_t hi, lo;
    split2(x0, x1, hi, lo);
    *(uint32_t*)(sm + baseHi + off) = hi;
    *(uint32_t*)(sm + baseLo + off) = lo;
}

__device__ __forceinline__ float silu_f(float z) {
    return z / (1.0f + __expf(-z));
}
__device__ __forceinline__ float emb_f(float tv, float p1, float p2, float d) {
    return tv * (__cosf(d * p1) + __sinf(d * p2));
}

__global__ void __launch_bounds__(NTH, 1)
fused_timestep_mlp_v7(const float* __restrict__ t,
                      const float* __restrict__ W1,
                      const float* __restrict__ b1,
                      const float* __restrict__ W2,
                      const float* __restrict__ b2,
                      float* __restrict__ out,
                      int n_tiles) {
    extern __shared__ char sm[];
    const uint32_t sb = smem_u32(sm);
    const int tid = threadIdx.x;
    const int wid = tid >> 5;
    const int lane = tid & 31;
    const int mg = wid & 3;   // rows mg*32..+31
    const int ng = wid >> 2;  // cols ng*32..+31

    // ---- weight init: split hi/lo bf16 swizzled; biases ----
    for (int e = tid * 4; e < DIM * DIM; e += NTH * 4) {
        const int row = e >> 7, k = e & 127;
        const float4 v1 = *(const float4*)(W1 + e);
        split_store(sm, OFF_W1H, OFF_W1L, row, k,     v1.x, v1.y);
        split_store(sm, OFF_W1H, OFF_W1L, row, k + 2, v1.z, v1.w);
        const float4 v2 = *(const float4*)(W2 + e);
        split_store(sm, OFF_W2H, OFF_W2L, row, k,     v2.x, v2.y);
        split_store(sm, OFF_W2H, OFF_W2L, row, k + 2, v2.z, v2.w);
    }
    if (tid < 128)      ((float*)(sm + OFF_B1))[tid] = b1[tid];
    else if (tid < 256) ((float*)(sm + OFF_B2))[tid - 128] = b2[tid - 128];
    __syncthreads();

    const float* sB1 = (const float*)(sm + OFF_B1);
    const float* sB2 = (const float*)(sm + OFF_B2);

    // lane geometry
    const int r0 = lane >> 2;                 // A/C frag row (and +8)
    const int kp = (lane & 3) * 2;            // A/C frag col-pair base
    const int g = lane >> 3, i = lane & 7;
    const int aRowLoc = ((g & 1) << 3) + i;   // smem-A ldsm row within 16
    const int aKoff   = (g >> 1) << 3;
    const int wRowLoc = ((g >> 1) << 3) + i;  // B ldsm n within 16
    const int wKoff   = (g & 1) << 3;

    float acc[2][4][4];

    for (int tile = blockIdx.x; tile < n_tiles; tile += gridDim.x) {
        const int rowBase = tile * DIM;

        // t values for this warp's 4 frag rows
        float tv[2][2], p1[2][2], p2[2][2];
#pragma unroll
        for (int mt = 0; mt < 2; ++mt) {
            tv[mt][0] = t[rowBase + mg * 32 + mt * 16 + r0];
            tv[mt][1] = t[rowBase + mg * 32 + mt * 16 + r0 + 8];
#pragma unroll
            for (int u = 0; u < 2; ++u) {
                p1[mt][u] = tv[mt][u] * (PI_F / 128.0f);
                p2[mt][u] = (1.0f - tv[mt][u]) * (PI_F / 128.0f);
            }
        }

#pragma unroll
        for (int mt = 0; mt < 2; ++mt)
#pragma unroll
            for (int nt = 0; nt < 4; ++nt)
#pragma unroll
                for (int q = 0; q < 4; ++q) acc[mt][nt][q] = 0.0f;

        // ---- GEMM1: A-frags from embedding (MUFU), B from smem ----
#pragma unroll
        for (int ks = 0; ks < 8; ++ks) {
            const int kb = ks * 16;
            uint32_t ah[2][4], al[2][4];
            const float dA = (float)(kb + kp), dB = dA + 1.0f;
            const float dC = dA + 8.0f,       dD = dA + 9.0f;
#pragma unroll
            for (int mt = 0; mt < 2; ++mt) {
                split2(emb_f(tv[mt][0], p1[mt][0], p2[mt][0], dA),
                       emb_f(tv[mt][0], p1[mt][0], p2[mt][0], dB), ah[mt][0], al[mt][0]);
                split2(emb_f(tv[mt][1], p1[mt][1], p2[mt][1], dA),
                       emb_f(tv[mt][1], p1[mt][1], p2[mt][1], dB), ah[mt][1], al[mt][1]);
                split2(emb_f(tv[mt][0], p1[mt][0], p2[mt][0], dC),
                       emb_f(tv[mt][0], p1[mt][0], p2[mt][0], dD), ah[mt][2], al[mt][2]);
                split2(emb_f(tv[mt][1], p1[mt][1], p2[mt][1], dC),
                       emb_f(tv[mt][1], p1[mt][1], p2[mt][1], dD), ah[mt][3], al[mt][3]);
            }
#pragma unroll
            for (int np = 0; np < 2; ++np) {
                const uint32_t wa = swz(ng * 32 + np * 16 + wRowLoc, kb + wKoff);
                uint32_t bh[4], bl[4];
                ldsm4(bh[0], bh[1], bh[2], bh[3], sb + OFF_W1H + wa);
                ldsm4(bl[0], bl[1], bl[2], bl[3], sb + OFF_W1L + wa);
                // 3 sweeps over 4 independent accumulators
#pragma unroll
                for (int mt = 0; mt < 2; ++mt) {
                    mma16816(acc[mt][2 * np],     ah[mt], bh[0], bh[1]);
                    mma16816(acc[mt][2 * np + 1], ah[mt], bh[2], bh[3]);
                }
#pragma unroll
                for (int mt = 0; mt < 2; ++mt) {
                    mma16816(acc[mt][2 * np],     al[mt], bh[0], bh[1]);
                    mma16816(acc[mt][2 * np + 1], al[mt], bh[2], bh[3]);
                }
#pragma unroll
                for (int mt = 0; mt < 2; ++mt) {
                    mma16816(acc[mt][2 * np],     ah[mt], bl[0], bl[1]);
                    mma16816(acc[mt][2 * np + 1], ah[mt], bl[2], bl[3]);
                }
            }
        }
        __syncthreads();  // prev-tile GEMM2 reads of sA done (and epi writes ordered)

        // ---- epilogue 1: bias + silu -> h split to smem ----
#pragma unroll
        for (int mt = 0; mt < 2; ++mt) {
#pragma unroll
            for (int ntl = 0; ntl < 4; ++ntl) {
                const int n  = ng * 32 + ntl * 8 + kp;
                const int rr = mg * 32 + mt * 16 + r0;
                const float bb0 = sB1[n], bb1 = sB1[n + 1];
                const float* c = acc[mt][ntl];
                split_store(sm, OFF_AH, OFF_AL, rr, n,
                            silu_f(c[0] + bb0), silu_f(c[1] + bb1));
                split_store(sm, OFF_AH, OFF_AL, rr + 8, n,
                            silu_f(c[2] + bb0), silu_f(c[3] + bb1));
            }
        }
        __syncthreads();

        // ---- GEMM2: A (h) from smem, B = W2 ----
#pragma unroll
        for (int mt = 0; mt < 2; ++mt)
#pragma unroll
            for (int nt = 0; nt < 4; ++nt)
#pragma unroll
                for (int q = 0; q < 4; ++q) acc[mt][nt][q] = 0.0f;

#pragma unroll
        for (int ks = 0; ks < 8; ++ks) {
            const int kb = ks * 16;
            uint32_t ah[2][4], al[2][4];
#pragma unroll
            for (int mt = 0; mt < 2; ++mt) {
                const uint32_t aa = swz(mg * 32 + mt * 16 + aRowLoc, kb + aKoff);
                ldsm4(ah[mt][0], ah[mt][1], ah[mt][2], ah[mt][3], sb + OFF_AH + aa);
                ldsm4(al[mt][0], al[mt][1], al[mt][2], al[mt][3], sb + OFF_AL + aa);
            }
#pragma unroll
            for (int np = 0; np < 2; ++np) {
                const uint32_t wa = swz(ng * 32 + np * 16 + wRowLoc, kb + wKoff);
                uint32_t bh[4], bl[4];
                ldsm4(bh[0], bh[1], bh[2], bh[3], sb + OFF_W2H + wa);
                ldsm4(bl[0], bl[1], bl[2], bl[3], sb + OFF_W2L + wa);
#pragma unroll
                for (int mt = 0; mt < 2; ++mt) {
                    mma16816(acc[mt][2 * np],     ah[mt], bh[0], bh[1]);
                    mma16816(acc[mt][2 * np + 1], ah[mt], bh[2], bh[3]);
                }
#pragma unroll
                for (int mt = 0; mt < 2; ++mt) {
                    mma16816(acc[mt][2 * np],     al[mt], bh[0], bh[1]);
                    mma16816(acc[mt][2 * np + 1], al[mt], bh[2], bh[3]);
                }
#pragma unroll
                for (int mt = 0; mt < 2; ++mt) {
                    mma16816(acc[mt][2 * np],     ah[mt], bl[0], bl[1]);
                    mma16816(acc[mt][2 * np + 1], ah[mt], bl[2], bl[3]);
                }
            }
        }

        // ---- epilogue 2: bias + silu -> gmem ----
#pragma unroll
        for (int mt = 0; mt < 2; ++mt) {
#pragma unroll
            for (int ntl = 0; ntl < 4; ++ntl) {
                const int n  = ng * 32 + ntl * 8 + kp;
                const int rr = rowBase + mg * 32 + mt * 16 + r0;
                const float bb0 = sB2[n], bb1 = sB2[n + 1];
                const float* c = acc[mt][ntl];
                *(float2*)(out + (size_t)rr * DIM + n) =
                    make_float2(silu_f(c[0] + bb0), silu_f(c[1] + bb1));
                *(float2*)(out + (size_t)(rr + 8) * DIM + n) =
                    make_float2(silu_f(c[2] + bb0), silu_f(c[3] + bb1));
            }
        }
        __syncthreads();  // GEMM2 sA reads done before next tile's epi1 writes
    }
}

extern "C" void kernel_launch(void* const* d_in, const int* in_sizes, int n_in,
                              void* d_out, int out_size) {
    const float* t  = (const float*)d_in[0];
    const float* W1 = (const float*)d_in[1];
    const float* b1 = (const float*)d_in[2];
    const float* W2 = (const float*)d_in[3];
    const float* b2 = (const float*)d_in[4];
    float* out = (float*)d_out;

    const int B = in_sizes[0];
    const int n_tiles = B / DIM;

    int nsm = 148;
    cudaDeviceGetAttribute(&nsm, cudaDevAttrMultiProcessorCount, 0);
    const int grid = nsm < n_tiles ? nsm : n_tiles;

    cudaFuncSetAttribute(fused_timestep_mlp_v7,
                         cudaFuncAttributeMaxDynamicSharedMemorySize, SMEM_TOTAL);

    fused_timestep_mlp_v7<<<grid, NTH, SMEM_TOTAL>>>(t, W1, b1, W2, b2, out, n_tiles);
}

// round 8
// speedup vs baseline: 1.5185x; 1.5185x over previous
#include <cuda_runtime.h>
#include <cuda_fp16.h>
#include <cstdint>

#define DIM 128
#define NTH 512
#define PI_F 3.14159265358979323846f

// ---- smem byte offsets (each 128x128 fp16 tile = 32768 B, swizzled) ----
#define OFF_W1H 0
#define OFF_W1L 32768
#define OFF_W2H 65536
#define OFF_W2L 98304
#define OFF_A   131072
#define OFF_B1  163840
#define OFF_B2  164352
#define SMEM_TOTAL 164864

// swizzled byte offset in a [128 rows x 128 k] fp16 tile, 256B/row
__device__ __forceinline__ uint32_t swz(int row, int kElem) {
    return (uint32_t)(row * 256) + (((uint32_t)(kElem * 2)) ^ (uint32_t)((row & 7) << 4));
}

__device__ __forceinline__ uint32_t smem_u32(const void* p) {
    uint32_t a;
    asm("{ .reg .u64 t; cvta.to.shared.u64 t, %1; cvt.u32.u64 %0, t; }" : "=r"(a) : "l"(p));
    return a;
}

__device__ __forceinline__ void ldsm4(uint32_t& r0, uint32_t& r1, uint32_t& r2, uint32_t& r3,
                                      uint32_t addr) {
    asm volatile("ldmatrix.sync.aligned.m8n8.x4.shared.b16 {%0,%1,%2,%3}, [%4];"
                 : "=r"(r0), "=r"(r1), "=r"(r2), "=r"(r3) : "r"(addr));
}

__device__ __forceinline__ void mma16816(float* c, const uint32_t* a, uint32_t b0, uint32_t b1) {
    asm volatile(
        "mma.sync.aligned.m16n8k16.row.col.f32.f16.f16.f32 "
        "{%0,%1,%2,%3}, {%4,%5,%6,%7}, {%8,%9}, {%0,%1,%2,%3};"
        : "+f"(c[0]), "+f"(c[1]), "+f"(c[2]), "+f"(c[3])
        : "r"(a[0]), "r"(a[1]), "r"(a[2]), "r"(a[3]), "r"(b0), "r"(b1));
}

__device__ __forceinline__ uint32_t pack2h(__half a, __half b) {
    return ((uint32_t)__half_as_ushort(b) << 16) | (uint32_t)__half_as_ushort(a);
}

// store fp16 pair (cols k,k+1) swizzled
__device__ __forceinline__ void store_h2(char* sm, int base, int row, int k,
                                         float x0, float x1) {
    *(uint32_t*)(sm + base + swz(row, k)) = pack2h(__float2half_rn(x0), __float2half_rn(x1));
}

// split weight pair into fp16 hi + fp16 residual tiles
__device__ __forceinline__ void split_store_w(char* sm, int baseHi, int baseLo,
                                              int row, int k, float x0, float x1) {
    const uint32_t off = swz(row, k);
    const __half h0 = __float2half_rn(x0), h1 = __float2half_rn(x1);
    const float r0 = x0 - __half2float(h0), r1 = x1 - __half2float(h1);
    *(uint32_t*)(sm + baseHi + off) = pack2h(h0, h1);
    *(uint32_t*)(sm + baseLo + off) = pack2h(__float2half_rn(r0), __float2half_rn(r1));
}

__device__ __forceinline__ float silu_f(float z) {
    return z / (1.0f + __expf(-z));
}

// One 128x128x128 GEMM, 2-pass fp16 split. Warp computes 32m x 32n.
__device__ __forceinline__ void gemm_warp(uint32_t sb, int offA, int offWh, int offWl,
                                          int mg, int ng, int lane,
                                          float acc[2][4][4]) {
#pragma unroll
    for (int mt = 0; mt < 2; ++mt)
#pragma unroll
        for (int nt = 0; nt < 4; ++nt)
#pragma unroll
            for (int q = 0; q < 4; ++q) acc[mt][nt][q] = 0.0f;

    const int g = lane >> 3, i = lane & 7;
    const int aRowLoc = ((g & 1) << 3) + i;
    const int aKoff   = (g >> 1) << 3;
    const int wRowLoc = ((g >> 1) << 3) + i;
    const int wKoff   = (g & 1) << 3;

#pragma unroll
    for (int ks = 0; ks < 8; ++ks) {
        const int k0 = ks * 16;
        uint32_t a[2][4];
#pragma unroll
        for (int mt = 0; mt < 2; ++mt) {
            const uint32_t aa = swz(mg * 32 + mt * 16 + aRowLoc, k0 + aKoff);
            ldsm4(a[mt][0], a[mt][1], a[mt][2], a[mt][3], sb + offA + aa);
        }
#pragma unroll
        for (int np = 0; np < 2; ++np) {
            const uint32_t wa = swz(ng * 32 + np * 16 + wRowLoc, k0 + wKoff);
            uint32_t bh[4], bl[4];
            ldsm4(bh[0], bh[1], bh[2], bh[3], sb + offWh + wa);
            ldsm4(bl[0], bl[1], bl[2], bl[3], sb + offWl + wa);
            // 2 sweeps over 4 independent accumulators
#pragma unroll
            for (int mt = 0; mt < 2; ++mt) {
                mma16816(acc[mt][2 * np],     a[mt], bh[0], bh[1]);
                mma16816(acc[mt][2 * np + 1], a[mt], bh[2], bh[3]);
            }
#pragma unroll
            for (int mt = 0; mt < 2; ++mt) {
                mma16816(acc[mt][2 * np],     a[mt], bl[0], bl[1]);
                mma16816(acc[mt][2 * np + 1], a[mt], bl[2], bl[3]);
            }
        }
    }
}

__global__ void __launch_bounds__(NTH, 1)
fused_timestep_mlp_h2(const float* __restrict__ t,
                      const float* __restrict__ W1,
                      const float* __restrict__ b1,
                      const float* __restrict__ W2,
                      const float* __restrict__ b2,
                      float* __restrict__ out,
                      int n_tiles) {
    extern __shared__ char sm[];
    const uint32_t sb = smem_u32(sm);
    const int tid = threadIdx.x;
    const int wid = tid >> 5;
    const int lane = tid & 31;
    const int mg = wid & 3;   // rows mg*32..+31
    const int ng = wid >> 2;  // cols ng*32..+31

    // ---- weight init: fp16 hi/lo split tiles; biases ----
    for (int e = tid * 4; e < DIM * DIM; e += NTH * 4) {
        const int row = e >> 7, k = e & 127;
        const float4 v1 = *(const float4*)(W1 + e);
        split_store_w(sm, OFF_W1H, OFF_W1L, row, k,     v1.x, v1.y);
        split_store_w(sm, OFF_W1H, OFF_W1L, row, k + 2, v1.z, v1.w);
        const float4 v2 = *(const float4*)(W2 + e);
        split_store_w(sm, OFF_W2H, OFF_W2L, row, k,     v2.x, v2.y);
        split_store_w(sm, OFF_W2H, OFF_W2L, row, k + 2, v2.z, v2.w);
    }
    if (tid < 128)      ((float*)(sm + OFF_B1))[tid] = b1[tid];
    else if (tid < 256) ((float*)(sm + OFF_B2))[tid - 128] = b2[tid - 128];
    __syncthreads();

    const float* sB1 = (const float*)(sm + OFF_B1);
    const float* sB2 = (const float*)(sm + OFF_B2);

    const int r0 = lane >> 2;        // C-frag row (and +8)
    const int kp = (lane & 3) * 2;   // C-frag col-pair base

    float acc[2][4][4];

    for (int tile = blockIdx.x; tile < n_tiles; tile += gridDim.x) {
        const int rowBase = tile * DIM;

        __syncthreads();  // prior GEMM2 smem reads done before A overwrite

        // ---- embedding -> A (fp16) ----
        {
            const int row = tid >> 2;
            const int kh  = (tid & 3) * 32;
            const float tv = t[rowBase + row];
            const float p1 = tv * (PI_F / 128.0f);
            const float p2 = (1.0f - tv) * (PI_F / 128.0f);
#pragma unroll 4
            for (int j = 0; j < 32; j += 2) {
                const float d0 = (float)(kh + j), d1 = (float)(kh + j + 1);
                const float e0 = tv * (__cosf(d0 * p1) + __sinf(d0 * p2));
                const float e1 = tv * (__cosf(d1 * p1) + __sinf(d1 * p2));
                store_h2(sm, OFF_A, row, kh + j, e0, e1);
            }
        }
        __syncthreads();

        // ---- layer 1 GEMM ----
        gemm_warp(sb, OFF_A, OFF_W1H, OFF_W1L, mg, ng, lane, acc);
        __syncthreads();  // all GEMM1 reads done before epi writes A

        // ---- epilogue 1: silu -> A (fp16) ----
#pragma unroll
        for (int mt = 0; mt < 2; ++mt) {
#pragma unroll
            for (int ntl = 0; ntl < 4; ++ntl) {
                const int n  = ng * 32 + ntl * 8 + kp;
                const int rr = mg * 32 + mt * 16 + r0;
                const float bb0 = sB1[n], bb1 = sB1[n + 1];
                const float* c = acc[mt][ntl];
                store_h2(sm, OFF_A, rr, n,     silu_f(c[0] + bb0), silu_f(c[1] + bb1));
                store_h2(sm, OFF_A, rr + 8, n, silu_f(c[2] + bb0), silu_f(c[3] + bb1));
            }
        }
        __syncthreads();

        // ---- layer 2 GEMM ----
        gemm_warp(sb, OFF_A, OFF_W2H, OFF_W2L, mg, ng, lane, acc);

        // ---- epilogue 2: silu -> gmem ----
#pragma unroll
        for (int mt = 0; mt < 2; ++mt) {
#pragma unroll
            for (int ntl = 0; ntl < 4; ++ntl) {
                const int n  = ng * 32 + ntl * 8 + kp;
                const int rr = rowBase + mg * 32 + mt * 16 + r0;
                const float bb0 = sB2[n], bb1 = sB2[n + 1];
                const float* c = acc[mt][ntl];
                *(float2*)(out + (size_t)rr * DIM + n) =
                    make_float2(silu_f(c[0] + bb0), silu_f(c[1] + bb1));
                *(float2*)(out + (size_t)(rr + 8) * DIM + n) =
                    make_float2(silu_f(c[2] + bb0), silu_f(c[3] + bb1));
            }
        }
    }
}

extern "C" void kernel_launch(void* const* d_in, const int* in_sizes, int n_in,
                              void* d_out, int out_size) {
    const float* t  = (const float*)d_in[0];
    const float* W1 = (const float*)d_in[1];
    const float* b1 = (const float*)d_in[2];
    const float* W2 = (const float*)d_in[3];
    const float* b2 = (const float*)d_in[4];
    float* out = (float*)d_out;

    const int B = in_sizes[0];
    const int n_tiles = B / DIM;

    int nsm = 148;
    cudaDeviceGetAttribute(&nsm, cudaDevAttrMultiProcessorCount, 0);
    const int grid = nsm < n_tiles ? nsm : n_tiles;

    cudaFuncSetAttribute(fused_timestep_mlp_h2,
                         cudaFuncAttributeMaxDynamicSharedMemorySize, SMEM_TOTAL);

    fused_timestep_mlp_h2<<<grid, NTH, SMEM_TOTAL>>>(t, W1, b1, W2, b2, out, n_tiles);
}

// round 9
// speedup vs baseline: 1.5746x; 1.0369x over previous
#include <cuda_runtime.h>
#include <cuda_fp16.h>
#include <cstdint>

#define DIM 128
#define NTH 512
#define PI_F 3.14159265358979323846f

// ---- smem byte offsets (each 128x128 fp16 tile = 32768 B, swizzled) ----
#define OFF_W1H 0
#define OFF_W1L 32768
#define OFF_W2H 65536
#define OFF_W2L 98304
#define OFF_A   131072
#define OFF_B1  163840
#define OFF_B2  164352
#define SMEM_TOTAL 164864

__device__ __forceinline__ uint32_t swz(int row, int kElem) {
    return (uint32_t)(row * 256) + (((uint32_t)(kElem * 2)) ^ (uint32_t)((row & 7) << 4));
}

__device__ __forceinline__ uint32_t smem_u32(const void* p) {
    uint32_t a;
    asm("{ .reg .u64 t; cvta.to.shared.u64 t, %1; cvt.u32.u64 %0, t; }" : "=r"(a) : "l"(p));
    return a;
}

// band barrier: 4 warps (128 threads) sharing the same m-band
__device__ __forceinline__ void band_sync(int id) {
    asm volatile("bar.sync %0, 128;" :: "r"(id) : "memory");
}

__device__ __forceinline__ void ldsm4(uint32_t& r0, uint32_t& r1, uint32_t& r2, uint32_t& r3,
                                      uint32_t addr) {
    asm volatile("ldmatrix.sync.aligned.m8n8.x4.shared.b16 {%0,%1,%2,%3}, [%4];"
                 : "=r"(r0), "=r"(r1), "=r"(r2), "=r"(r3) : "r"(addr));
}

__device__ __forceinline__ void mma16816(float* c, const uint32_t* a, uint32_t b0, uint32_t b1) {
    asm volatile(
        "mma.sync.aligned.m16n8k16.row.col.f32.f16.f16.f32 "
        "{%0,%1,%2,%3}, {%4,%5,%6,%7}, {%8,%9}, {%0,%1,%2,%3};"
        : "+f"(c[0]), "+f"(c[1]), "+f"(c[2]), "+f"(c[3])
        : "r"(a[0]), "r"(a[1]), "r"(a[2]), "r"(a[3]), "r"(b0), "r"(b1));
}

__device__ __forceinline__ uint32_t pack2h(__half a, __half b) {
    return ((uint32_t)__half_as_ushort(b) << 16) | (uint32_t)__half_as_ushort(a);
}

__device__ __forceinline__ void store_h2(char* sm, int base, int row, int k,
                                         float x0, float x1) {
    *(uint32_t*)(sm + base + swz(row, k)) = pack2h(__float2half_rn(x0), __float2half_rn(x1));
}

__device__ __forceinline__ void split_store_w(char* sm, int baseHi, int baseLo,
                                              int row, int k, float x0, float x1) {
    const uint32_t off = swz(row, k);
    const __half h0 = __float2half_rn(x0), h1 = __float2half_rn(x1);
    const float r0 = x0 - __half2float(h0), r1 = x1 - __half2float(h1);
    *(uint32_t*)(sm + baseHi + off) = pack2h(h0, h1);
    *(uint32_t*)(sm + baseLo + off) = pack2h(__float2half_rn(r0), __float2half_rn(r1));
}

__device__ __forceinline__ float silu_f(float z) {
    return z / (1.0f + __expf(-z));
}

// One 128x(32n)x128 warp GEMM, 2-pass fp16 split. Warp computes 32m x 32n.
__device__ __forceinline__ void gemm_warp(uint32_t sb, int offA, int offWh, int offWl,
                                          int mg, int ng, int lane,
                                          float acc[2][4][4]) {
#pragma unroll
    for (int mt = 0; mt < 2; ++mt)
#pragma unroll
        for (int nt = 0; nt < 4; ++nt)
#pragma unroll
            for (int q = 0; q < 4; ++q) acc[mt][nt][q] = 0.0f;

    const int g = lane >> 3, i = lane & 7;
    const int aRowLoc = ((g & 1) << 3) + i;
    const int aKoff   = (g >> 1) << 3;
    const int wRowLoc = ((g >> 1) << 3) + i;
    const int wKoff   = (g & 1) << 3;

#pragma unroll
    for (int ks = 0; ks < 8; ++ks) {
        const int k0 = ks * 16;
        uint32_t a[2][4];
#pragma unroll
        for (int mt = 0; mt < 2; ++mt) {
            const uint32_t aa = swz(mg * 32 + mt * 16 + aRowLoc, k0 + aKoff);
            ldsm4(a[mt][0], a[mt][1], a[mt][2], a[mt][3], sb + offA + aa);
        }
#pragma unroll
        for (int np = 0; np < 2; ++np) {
            const uint32_t wa = swz(ng * 32 + np * 16 + wRowLoc, k0 + wKoff);
            uint32_t bh[4], bl[4];
            ldsm4(bh[0], bh[1], bh[2], bh[3], sb + offWh + wa);
            ldsm4(bl[0], bl[1], bl[2], bl[3], sb + offWl + wa);
#pragma unroll
            for (int mt = 0; mt < 2; ++mt) {
                mma16816(acc[mt][2 * np],     a[mt], bh[0], bh[1]);
                mma16816(acc[mt][2 * np + 1], a[mt], bh[2], bh[3]);
            }
#pragma unroll
            for (int mt = 0; mt < 2; ++mt) {
                mma16816(acc[mt][2 * np],     a[mt], bl[0], bl[1]);
                mma16816(acc[mt][2 * np + 1], a[mt], bl[2], bl[3]);
            }
        }
    }
}

__global__ void __launch_bounds__(NTH, 1)
fused_timestep_mlp_band(const float* __restrict__ t,
                        const float* __restrict__ W1,
                        const float* __restrict__ b1,
                        const float* __restrict__ W2,
                        const float* __restrict__ b2,
                        float* __restrict__ out,
                        int n_tiles) {
    extern __shared__ char sm[];
    const uint32_t sb = smem_u32(sm);
    const int tid = threadIdx.x;
    const int wid = tid >> 5;
    const int lane = tid & 31;
    const int mg = wid & 3;   // band: rows mg*32..+31
    const int ng = wid >> 2;  // cols ng*32..+31
    const int bar_id = mg + 1;
    const int band_tid = ng * 32 + lane;   // 0..127 within band

    // ---- weight init: fp16 hi/lo split tiles; biases ----
    for (int e = tid * 4; e < DIM * DIM; e += NTH * 4) {
        const int row = e >> 7, k = e & 127;
        const float4 v1 = *(const float4*)(W1 + e);
        split_store_w(sm, OFF_W1H, OFF_W1L, row, k,     v1.x, v1.y);
        split_store_w(sm, OFF_W1H, OFF_W1L, row, k + 2, v1.z, v1.w);
        const float4 v2 = *(const float4*)(W2 + e);
        split_store_w(sm, OFF_W2H, OFF_W2L, row, k,     v2.x, v2.y);
        split_store_w(sm, OFF_W2H, OFF_W2L, row, k + 2, v2.z, v2.w);
    }
    if (tid < 128)      ((float*)(sm + OFF_B1))[tid] = b1[tid];
    else if (tid < 256) ((float*)(sm + OFF_B2))[tid - 128] = b2[tid - 128];
    __syncthreads();  // only full-CTA sync

    const float* sB1 = (const float*)(sm + OFF_B1);
    const float* sB2 = (const float*)(sm + OFF_B2);

    const int r0 = lane >> 2;        // C-frag row (and +8)
    const int kp = (lane & 3) * 2;   // C-frag col-pair base

    // emb geometry (band-local): 128 threads cover 32 rows x 128 k
    const int eRow = mg * 32 + (band_tid >> 2);
    const int eKh  = (band_tid & 3) * 32;

    float acc[2][4][4];

    for (int tile = blockIdx.x; tile < n_tiles; tile += gridDim.x) {
        const int rowBase = tile * DIM;

        band_sync(bar_id);  // band's GEMM2 reads of A done before overwrite

        // ---- embedding -> A band rows (fp16) ----
        {
            const float tv = t[rowBase + eRow];
            const float p1 = tv * (PI_F / 128.0f);
            const float p2 = (1.0f - tv) * (PI_F / 128.0f);
#pragma unroll 4
            for (int j = 0; j < 32; j += 2) {
                const float d0 = (float)(eKh + j), d1 = (float)(eKh + j + 1);
                const float e0 = tv * (__cosf(d0 * p1) + __sinf(d0 * p2));
                const float e1 = tv * (__cosf(d1 * p1) + __sinf(d1 * p2));
                store_h2(sm, OFF_A, eRow, eKh + j, e0, e1);
            }
        }
        band_sync(bar_id);

        // ---- layer 1 GEMM (reads A band rows, W1) ----
        gemm_warp(sb, OFF_A, OFF_W1H, OFF_W1L, mg, ng, lane, acc);
        band_sync(bar_id);  // band GEMM1 reads done before epi writes A band

        // ---- epilogue 1: silu -> A band rows (fp16) ----
#pragma unroll
        for (int mt = 0; mt < 2; ++mt) {
#pragma unroll
            for (int ntl = 0; ntl < 4; ++ntl) {
                const int n  = ng * 32 + ntl * 8 + kp;
                const int rr = mg * 32 + mt * 16 + r0;
                const float bb0 = sB1[n], bb1 = sB1[n + 1];
                const float* c = acc[mt][ntl];
                store_h2(sm, OFF_A, rr, n,     silu_f(c[0] + bb0), silu_f(c[1] + bb1));
                store_h2(sm, OFF_A, rr + 8, n, silu_f(c[2] + bb0), silu_f(c[3] + bb1));
            }
        }
        band_sync(bar_id);

        // ---- layer 2 GEMM ----
        gemm_warp(sb, OFF_A, OFF_W2H, OFF_W2L, mg, ng, lane, acc);

        // ---- epilogue 2: silu -> gmem ----
#pragma unroll
        for (int mt = 0; mt < 2; ++mt) {
#pragma unroll
            for (int ntl = 0; ntl < 4; ++ntl) {
                const int n  = ng * 32 + ntl * 8 + kp;
                const int rr = rowBase + mg * 32 + mt * 16 + r0;
                const float bb0 = sB2[n], bb1 = sB2[n + 1];
                const float* c = acc[mt][ntl];
                *(float2*)(out + (size_t)rr * DIM + n) =
                    make_float2(silu_f(c[0] + bb0), silu_f(c[1] + bb1));
                *(float2*)(out + (size_t)(rr + 8) * DIM + n) =
                    make_float2(silu_f(c[2] + bb0), silu_f(c[3] + bb1));
            }
        }
    }
}

extern "C" void kernel_launch(void* const* d_in, const int* in_sizes, int n_in,
                              void* d_out, int out_size) {
    const float* t  = (const float*)d_in[0];
    const float* W1 = (const float*)d_in[1];
    const float* b1 = (const float*)d_in[2];
    const float* W2 = (const float*)d_in[3];
    const float* b2 = (const float*)d_in[4];
    float* out = (float*)d_out;

    const int B = in_sizes[0];
    const int n_tiles = B / DIM;

    int nsm = 148;
    cudaDeviceGetAttribute(&nsm, cudaDevAttrMultiProcessorCount, 0);
    const int grid = nsm < n_tiles ? nsm : n_tiles;

    cudaFuncSetAttribute(fused_timestep_mlp_band,
                         cudaFuncAttributeMaxDynamicSharedMemorySize, SMEM_TOTAL);

    fused_timestep_mlp_band<<<grid, NTH, SMEM_TOTAL>>>(t, W1, b1, W2, b2, out, n_tiles);
}

// round 10
// speedup vs baseline: 1.9100x; 1.2131x over previous
#include <cuda_runtime.h>
#include <cuda_fp16.h>
#include <cstdint>

#define DIM 128
#define NTH 512
#define PI_F 3.14159265358979323846f

// ---- smem byte offsets (each 128x128 fp16 tile = 32768 B, swizzled) ----
#define OFF_W1  0
#define OFF_W2  32768
#define OFF_A   65536
#define OFF_B1  98304
#define OFF_B2  98816
#define SMEM_TOTAL 99328

__device__ __forceinline__ uint32_t swz(int row, int kElem) {
    return (uint32_t)(row * 256) + (((uint32_t)(kElem * 2)) ^ (uint32_t)((row & 7) << 4));
}

__device__ __forceinline__ uint32_t smem_u32(const void* p) {
    uint32_t a;
    asm("{ .reg .u64 t; cvta.to.shared.u64 t, %1; cvt.u32.u64 %0, t; }" : "=r"(a) : "l"(p));
    return a;
}

// band barrier: 4 warps (128 threads) sharing the same m-band
__device__ __forceinline__ void band_sync(int id) {
    asm volatile("bar.sync %0, 128;" :: "r"(id) : "memory");
}

__device__ __forceinline__ void ldsm4(uint32_t& r0, uint32_t& r1, uint32_t& r2, uint32_t& r3,
                                      uint32_t addr) {
    asm volatile("ldmatrix.sync.aligned.m8n8.x4.shared.b16 {%0,%1,%2,%3}, [%4];"
                 : "=r"(r0), "=r"(r1), "=r"(r2), "=r"(r3) : "r"(addr));
}

__device__ __forceinline__ void mma16816(float* c, const uint32_t* a, uint32_t b0, uint32_t b1) {
    asm volatile(
        "mma.sync.aligned.m16n8k16.row.col.f32.f16.f16.f32 "
        "{%0,%1,%2,%3}, {%4,%5,%6,%7}, {%8,%9}, {%0,%1,%2,%3};"
        : "+f"(c[0]), "+f"(c[1]), "+f"(c[2]), "+f"(c[3])
        : "r"(a[0]), "r"(a[1]), "r"(a[2]), "r"(a[3]), "r"(b0), "r"(b1));
}

__device__ __forceinline__ uint32_t pack2h(__half a, __half b) {
    return ((uint32_t)__half_as_ushort(b) << 16) | (uint32_t)__half_as_ushort(a);
}

__device__ __forceinline__ void store_h2(char* sm, int base, int row, int k,
                                         float x0, float x1) {
    *(uint32_t*)(sm + base + swz(row, k)) = pack2h(__float2half_rn(x0), __float2half_rn(x1));
}

__device__ __forceinline__ float silu_f(float z) {
    return z / (1.0f + __expf(-z));
}

// One 128x(32n)x128 warp GEMM, single-pass fp16. Warp computes 32m x 32n.
__device__ __forceinline__ void gemm_warp(uint32_t sb, int offA, int offW,
                                          int mg, int ng, int lane,
                                          float acc[2][4][4]) {
#pragma unroll
    for (int mt = 0; mt < 2; ++mt)
#pragma unroll
        for (int nt = 0; nt < 4; ++nt)
#pragma unroll
            for (int q = 0; q < 4; ++q) acc[mt][nt][q] = 0.0f;

    const int g = lane >> 3, i = lane & 7;
    const int aRowLoc = ((g & 1) << 3) + i;
    const int aKoff   = (g >> 1) << 3;
    const int wRowLoc = ((g >> 1) << 3) + i;
    const int wKoff   = (g & 1) << 3;

#pragma unroll
    for (int ks = 0; ks < 8; ++ks) {
        const int k0 = ks * 16;
        uint32_t a[2][4];
#pragma unroll
        for (int mt = 0; mt < 2; ++mt) {
            const uint32_t aa = swz(mg * 32 + mt * 16 + aRowLoc, k0 + aKoff);
            ldsm4(a[mt][0], a[mt][1], a[mt][2], a[mt][3], sb + offA + aa);
        }
#pragma unroll
        for (int np = 0; np < 2; ++np) {
            const uint32_t wa = swz(ng * 32 + np * 16 + wRowLoc, k0 + wKoff);
            uint32_t b[4];
            ldsm4(b[0], b[1], b[2], b[3], sb + offW + wa);
#pragma unroll
            for (int mt = 0; mt < 2; ++mt) {
                mma16816(acc[mt][2 * np],     a[mt], b[0], b[1]);
                mma16816(acc[mt][2 * np + 1], a[mt], b[2], b[3]);
            }
        }
    }
}

__global__ void __launch_bounds__(NTH, 1)
fused_timestep_mlp_1p(const float* __restrict__ t,
                      const float* __restrict__ W1,
                      const float* __restrict__ b1,
                      const float* __restrict__ W2,
                      const float* __restrict__ b2,
                      float* __restrict__ out,
                      int n_tiles) {
    extern __shared__ char sm[];
    const uint32_t sb = smem_u32(sm);
    const int tid = threadIdx.x;
    const int wid = tid >> 5;
    const int lane = tid & 31;
    const int mg = wid & 3;   // band: rows mg*32..+31
    const int ng = wid >> 2;  // cols ng*32..+31
    const int bar_id = mg + 1;
    const int band_tid = ng * 32 + lane;   // 0..127 within band

    // ---- weight init: fp16 tiles; biases ----
    for (int e = tid * 4; e < DIM * DIM; e += NTH * 4) {
        const int row = e >> 7, k = e & 127;
        const float4 v1 = *(const float4*)(W1 + e);
        store_h2(sm, OFF_W1, row, k,     v1.x, v1.y);
        store_h2(sm, OFF_W1, row, k + 2, v1.z, v1.w);
        const float4 v2 = *(const float4*)(W2 + e);
        store_h2(sm, OFF_W2, row, k,     v2.x, v2.y);
        store_h2(sm, OFF_W2, row, k + 2, v2.z, v2.w);
    }
    if (tid < 128)      ((float*)(sm + OFF_B1))[tid] = b1[tid];
    else if (tid < 256) ((float*)(sm + OFF_B2))[tid - 128] = b2[tid - 128];
    __syncthreads();  // only full-CTA sync

    const float* sB1 = (const float*)(sm + OFF_B1);
    const float* sB2 = (const float*)(sm + OFF_B2);

    const int r0 = lane >> 2;        // C-frag row (and +8)
    const int kp = (lane & 3) * 2;   // C-frag col-pair base

    // emb geometry (band-local): 128 threads cover 32 rows x 128 k
    const int eRow = mg * 32 + (band_tid >> 2);
    const int eKh  = (band_tid & 3) * 32;

    float acc[2][4][4];

    for (int tile = blockIdx.x; tile < n_tiles; tile += gridDim.x) {
        const int rowBase = tile * DIM;

        band_sync(bar_id);  // band's GEMM2 reads of A done before overwrite

        // ---- embedding -> A band rows (fp16) ----
        {
            const float tv = t[rowBase + eRow];
            const float p1 = tv * (PI_F / 128.0f);
            const float p2 = (1.0f - tv) * (PI_F / 128.0f);
#pragma unroll 4
            for (int j = 0; j < 32; j += 2) {
                const float d0 = (float)(eKh + j), d1 = (float)(eKh + j + 1);
                const float e0 = tv * (__cosf(d0 * p1) + __sinf(d0 * p2));
                const float e1 = tv * (__cosf(d1 * p1) + __sinf(d1 * p2));
                store_h2(sm, OFF_A, eRow, eKh + j, e0, e1);
            }
        }
        band_sync(bar_id);

        // ---- layer 1 GEMM ----
        gemm_warp(sb, OFF_A, OFF_W1, mg, ng, lane, acc);
        band_sync(bar_id);  // band GEMM1 reads done before epi writes A band

        // ---- epilogue 1: silu -> A band rows (fp16) ----
#pragma unroll
        for (int mt = 0; mt < 2; ++mt) {
#pragma unroll
            for (int ntl = 0; ntl < 4; ++ntl) {
                const int n  = ng * 32 + ntl * 8 + kp;
                const int rr = mg * 32 + mt * 16 + r0;
                const float bb0 = sB1[n], bb1 = sB1[n + 1];
                const float* c = acc[mt][ntl];
                store_h2(sm, OFF_A, rr, n,     silu_f(c[0] + bb0), silu_f(c[1] + bb1));
                store_h2(sm, OFF_A, rr + 8, n, silu_f(c[2] + bb0), silu_f(c[3] + bb1));
            }
        }
        band_sync(bar_id);

        // ---- layer 2 GEMM ----
        gemm_warp(sb, OFF_A, OFF_W2, mg, ng, lane, acc);

        // ---- epilogue 2: silu -> gmem ----
#pragma unroll
        for (int mt = 0; mt < 2; ++mt) {
#pragma unroll
            for (int ntl = 0; ntl < 4; ++ntl) {
                const int n  = ng * 32 + ntl * 8 + kp;
                const int rr = rowBase + mg * 32 + mt * 16 + r0;
                const float bb0 = sB2[n], bb1 = sB2[n + 1];
                const float* c = acc[mt][ntl];
                *(float2*)(out + (size_t)rr * DIM + n) =
                    make_float2(silu_f(c[0] + bb0), silu_f(c[1] + bb1));
                *(float2*)(out + (size_t)(rr + 8) * DIM + n) =
                    make_float2(silu_f(c[2] + bb0), silu_f(c[3] + bb1));
            }
        }
    }
}

extern "C" void kernel_launch(void* const* d_in, const int* in_sizes, int n_in,
                              void* d_out, int out_size) {
    const float* t  = (const float*)d_in[0];
    const float* W1 = (const float*)d_in[1];
    const float* b1 = (const float*)d_in[2];
    const float* W2 = (const float*)d_in[3];
    const float* b2 = (const float*)d_in[4];
    float* out = (float*)d_out;

    const int B = in_sizes[0];
    const int n_tiles = B / DIM;

    int nsm = 148;
    cudaDeviceGetAttribute(&nsm, cudaDevAttrMultiProcessorCount, 0);
    const int grid = nsm < n_tiles ? nsm : n_tiles;

    cudaFuncSetAttribute(fused_timestep_mlp_1p,
                         cudaFuncAttributeMaxDynamicSharedMemorySize, SMEM_TOTAL);

    fused_timestep_mlp_1p<<<grid, NTH, SMEM_TOTAL>>>(t, W1, b1, W2, b2, out, n_tiles);
}

// round 11
// speedup vs baseline: 3.1405x; 1.6442x over previous
#include <cuda_runtime.h>
#include <cuda_fp16.h>
#include <cstdint>

#define DIM 128
#define NTH 512
#define WARPS 16
#define PI_F 3.14159265358979323846f

// ---- smem: two 128x128 fp16 weight tiles (swizzled) + biases ----
#define OFF_W1  0
#define OFF_W2  32768
#define OFF_B1  65536
#define OFF_B2  66048
#define SMEM_TOTAL 66560

__device__ __forceinline__ uint32_t swz(int row, int kElem) {
    return (uint32_t)(row * 256) + (((uint32_t)(kElem * 2)) ^ (uint32_t)((row & 7) << 4));
}

__device__ __forceinline__ uint32_t smem_u32(const void* p) {
    uint32_t a;
    asm("{ .reg .u64 t; cvta.to.shared.u64 t, %1; cvt.u32.u64 %0, t; }" : "=r"(a) : "l"(p));
    return a;
}

__device__ __forceinline__ void ldsm4(uint32_t& r0, uint32_t& r1, uint32_t& r2, uint32_t& r3,
                                      uint32_t addr) {
    asm volatile("ldmatrix.sync.aligned.m8n8.x4.shared.b16 {%0,%1,%2,%3}, [%4];"
                 : "=r"(r0), "=r"(r1), "=r"(r2), "=r"(r3) : "r"(addr));
}

__device__ __forceinline__ void mma16816(float* c, const uint32_t* a, uint32_t b0, uint32_t b1) {
    asm volatile(
        "mma.sync.aligned.m16n8k16.row.col.f32.f16.f16.f32 "
        "{%0,%1,%2,%3}, {%4,%5,%6,%7}, {%8,%9}, {%0,%1,%2,%3};"
        : "+f"(c[0]), "+f"(c[1]), "+f"(c[2]), "+f"(c[3])
        : "r"(a[0]), "r"(a[1]), "r"(a[2]), "r"(a[3]), "r"(b0), "r"(b1));
}

__device__ __forceinline__ uint32_t pack2h(float x0, float x1) {
    return ((uint32_t)__half_as_ushort(__float2half_rn(x1)) << 16) |
           (uint32_t)__half_as_ushort(__float2half_rn(x0));
}

__device__ __forceinline__ void store_h2(char* sm, int base, int row, int k,
                                         float x0, float x1) {
    *(uint32_t*)(sm + base + swz(row, k)) = pack2h(x0, x1);
}

__device__ __forceinline__ float silu_f(float z) {
    return __fdividef(z, 1.0f + __expf(-z));
}
__device__ __forceinline__ float emb_f(float tv, float p1, float p2, float d) {
    return tv * (__cosf(d * p1) + __sinf(d * p2));
}

__global__ void __launch_bounds__(NTH, 1)
fused_timestep_mlp_wa(const float* __restrict__ t,
                      const float* __restrict__ W1,
                      const float* __restrict__ b1,
                      const float* __restrict__ W2,
                      const float* __restrict__ b2,
                      float* __restrict__ out,
                      int n_chunks) {
    extern __shared__ char sm[];
    const uint32_t sb = smem_u32(sm);
    const int tid = threadIdx.x;
    const int wid = tid >> 5;
    const int lane = tid & 31;

    // ---- weight init: fp16 swizzled tiles; biases ----
    for (int e = tid * 4; e < DIM * DIM; e += NTH * 4) {
        const int row = e >> 7, k = e & 127;
        const float4 v1 = *(const float4*)(W1 + e);
        store_h2(sm, OFF_W1, row, k,     v1.x, v1.y);
        store_h2(sm, OFF_W1, row, k + 2, v1.z, v1.w);
        const float4 v2 = *(const float4*)(W2 + e);
        store_h2(sm, OFF_W2, row, k,     v2.x, v2.y);
        store_h2(sm, OFF_W2, row, k + 2, v2.z, v2.w);
    }
    if (tid < 128)      ((float*)(sm + OFF_B1))[tid] = b1[tid];
    else if (tid < 256) ((float*)(sm + OFF_B2))[tid - 128] = b2[tid - 128];
    __syncthreads();  // only sync in the kernel

    const float* sB1 = (const float*)(sm + OFF_B1);
    const float* sB2 = (const float*)(sm + OFF_B2);

    // lane geometry
    const int r0 = lane >> 2;                 // frag row (and +8)
    const int kp = (lane & 3) * 2;            // frag col-pair base
    const int g = lane >> 3, i = lane & 7;
    const int wRowLoc = ((g >> 1) << 3) + i;  // B-frag n within 16
    const int wKoff   = (g & 1) << 3;         // B-frag k half

    for (int chunk = blockIdx.x * WARPS + wid; chunk < n_chunks;
         chunk += gridDim.x * WARPS) {
        const int rowBase = chunk * 16;

        const float tv0 = t[rowBase + r0];
        const float tv1 = t[rowBase + r0 + 8];
        const float p10 = tv0 * (PI_F / 128.0f), p20 = (1.0f - tv0) * (PI_F / 128.0f);
        const float p11 = tv1 * (PI_F / 128.0f), p21 = (1.0f - tv1) * (PI_F / 128.0f);

        float acc[16][4];
#pragma unroll
        for (int nt = 0; nt < 16; ++nt)
#pragma unroll
            for (int q = 0; q < 4; ++q) acc[nt][q] = 0.0f;

        // ---- GEMM1: A-frags from embedding (MUFU), B = W1 from smem ----
#pragma unroll
        for (int ks = 0; ks < 8; ++ks) {
            const int kb = ks * 16;
            const float dA = (float)(kb + kp), dB = dA + 1.0f;
            const float dC = dA + 8.0f,       dD = dA + 9.0f;
            uint32_t a[4];
            a[0] = pack2h(emb_f(tv0, p10, p20, dA), emb_f(tv0, p10, p20, dB));
            a[1] = pack2h(emb_f(tv1, p11, p21, dA), emb_f(tv1, p11, p21, dB));
            a[2] = pack2h(emb_f(tv0, p10, p20, dC), emb_f(tv0, p10, p20, dD));
            a[3] = pack2h(emb_f(tv1, p11, p21, dC), emb_f(tv1, p11, p21, dD));
#pragma unroll
            for (int np = 0; np < 8; ++np) {
                const uint32_t wa = swz(np * 16 + wRowLoc, kb + wKoff);
                uint32_t b[4];
                ldsm4(b[0], b[1], b[2], b[3], sb + OFF_W1 + wa);
                mma16816(acc[2 * np],     a, b[0], b[1]);
                mma16816(acc[2 * np + 1], a, b[2], b[3]);
            }
        }

        // ---- epilogue 1 in registers: bias + silu -> layer-2 A-frags ----
        uint32_t ha[8][4];
#pragma unroll
        for (int ks = 0; ks < 8; ++ks) {
            const float2 bA = *(const float2*)(sB1 + ks * 16 + kp);
            const float2 bB = *(const float2*)(sB1 + ks * 16 + 8 + kp);
            const float* c0 = acc[2 * ks];
            const float* c1 = acc[2 * ks + 1];
            ha[ks][0] = pack2h(silu_f(c0[0] + bA.x), silu_f(c0[1] + bA.y));
            ha[ks][1] = pack2h(silu_f(c0[2] + bA.x), silu_f(c0[3] + bA.y));
            ha[ks][2] = pack2h(silu_f(c1[0] + bB.x), silu_f(c1[1] + bB.y));
            ha[ks][3] = pack2h(silu_f(c1[2] + bB.x), silu_f(c1[3] + bB.y));
        }

        // ---- GEMM2: A = h (registers), B = W2 from smem ----
#pragma unroll
        for (int nt = 0; nt < 16; ++nt)
#pragma unroll
            for (int q = 0; q < 4; ++q) acc[nt][q] = 0.0f;
#pragma unroll
        for (int ks = 0; ks < 8; ++ks) {
            const int kb = ks * 16;
#pragma unroll
            for (int np = 0; np < 8; ++np) {
                const uint32_t wa = swz(np * 16 + wRowLoc, kb + wKoff);
                uint32_t b[4];
                ldsm4(b[0], b[1], b[2], b[3], sb + OFF_W2 + wa);
                mma16816(acc[2 * np],     ha[ks], b[0], b[1]);
                mma16816(acc[2 * np + 1], ha[ks], b[2], b[3]);
            }
        }

        // ---- epilogue 2: bias + silu -> gmem ----
        float* o0 = out + (size_t)(rowBase + r0) * DIM;
        float* o1 = out + (size_t)(rowBase + r0 + 8) * DIM;
#pragma unroll
        for (int nt = 0; nt < 16; ++nt) {
            const int c = nt * 8 + kp;
            const float2 bb = *(const float2*)(sB2 + c);
            const float* a4 = acc[nt];
            *(float2*)(o0 + c) = make_float2(silu_f(a4[0] + bb.x), silu_f(a4[1] + bb.y));
            *(float2*)(o1 + c) = make_float2(silu_f(a4[2] + bb.x), silu_f(a4[3] + bb.y));
        }
    }
}

extern "C" void kernel_launch(void* const* d_in, const int* in_sizes, int n_in,
                              void* d_out, int out_size) {
    const float* t  = (const float*)d_in[0];
    const float* W1 = (const float*)d_in[1];
    const float* b1 = (const float*)d_in[2];
    const float* W2 = (const float*)d_in[3];
    const float* b2 = (const float*)d_in[4];
    float* out = (float*)d_out;

    const int B = in_sizes[0];
    const int n_chunks = B / 16;

    int nsm = 148;
    cudaDeviceGetAttribute(&nsm, cudaDevAttrMultiProcessorCount, 0);

    cudaFuncSetAttribute(fused_timestep_mlp_wa,
                         cudaFuncAttributeMaxDynamicSharedMemorySize, SMEM_TOTAL);

    fused_timestep_mlp_wa<<<nsm, NTH, SMEM_TOTAL>>>(t, W1, b1, W2, b2, out, n_chunks);
}